// round 17
// speedup vs baseline: 7.4744x; 1.0060x over previous
#include <cuda_runtime.h>
#include <cuda_fp16.h>
#include <math.h>
#include <stdint.h>

// ---------------------------------------------------------------------------
// EncoderBlock: B=4, L=1024, D=1024, F=4096, H=16, dh=64
// Round 16: forked-stream weight conversion (overlaps QKV+attention);
// attention 3-stage KV pipeline; x-cvt fused into qkv-weight cvt.
// ---------------------------------------------------------------------------

#define LSEQ 1024
#define DMODEL 1024
#define BATCH 4
#define NHEAD 16
#define DHEAD 64
#define FFDIM 4096
#define BHDIM 64
#define MROWS 4096
#define LOG2E 1.4426950408889634f
#define SLAB_ELEMS (MROWS * DMODEL)
#define ONES_H2 0x3C003C00u

// ---- fp32 scratch ----------------------------------------------------------
__device__ float g_attp[BATCH * LSEQ * DMODEL];
__device__ float g_attout[BATCH * LSEQ * DMODEL];
__device__ float g_ff[BATCH * LSEQ * DMODEL];
__device__ float g_bqkv[3 * DMODEL];

// ---- fp16 scratch -----------------------------------------------------------
__device__ __half g_xf[SLAB_ELEMS];
__device__ __half g_wqkv[3 * DMODEL * DMODEL];
__device__ __half g_wo[DMODEL * DMODEL];
__device__ __half g_w1[FFDIM * DMODEL];
__device__ __half g_w2[DMODEL * FFDIM];
__device__ __half g_qkv[3 * SLAB_ELEMS];
__device__ __half g_avf[SLAB_ELEMS];
__device__ __half g_aof[SLAB_ELEMS];
__device__ __half g_h1f[(size_t)MROWS * FFDIM];

// ============================================================================
// helpers
// ============================================================================
__device__ __forceinline__ uint32_t smem_u32(const void* p) {
    uint32_t a;
    asm("{ .reg .u64 t; cvta.to.shared.u64 t, %1; cvt.u32.u64 %0, t; }"
        : "=r"(a) : "l"(p));
    return a;
}
__device__ __forceinline__ void cp16(uint32_t dst, const void* src) {
    asm volatile("cp.async.cg.shared.global [%0], [%1], 16;" :: "r"(dst), "l"(src));
}
__device__ __forceinline__ void ldsm_x4(uint32_t& r0, uint32_t& r1,
                                        uint32_t& r2, uint32_t& r3, uint32_t a) {
    asm volatile("ldmatrix.sync.aligned.m8n8.x4.shared.b16 {%0,%1,%2,%3}, [%4];"
                 : "=r"(r0), "=r"(r1), "=r"(r2), "=r"(r3) : "r"(a));
}
__device__ __forceinline__ void ldsm_x4t(uint32_t& r0, uint32_t& r1,
                                         uint32_t& r2, uint32_t& r3, uint32_t a) {
    asm volatile("ldmatrix.sync.aligned.m8n8.x4.trans.shared.b16 {%0,%1,%2,%3}, [%4];"
                 : "=r"(r0), "=r"(r1), "=r"(r2), "=r"(r3) : "r"(a));
}
__device__ __forceinline__ void mma_f16(float* c, const uint32_t* a, const uint32_t* b) {
    asm volatile(
        "mma.sync.aligned.m16n8k16.row.col.f32.f16.f16.f32 "
        "{%0,%1,%2,%3}, {%4,%5,%6,%7}, {%8,%9}, {%0,%1,%2,%3};"
        : "+f"(c[0]), "+f"(c[1]), "+f"(c[2]), "+f"(c[3])
        : "r"(a[0]), "r"(a[1]), "r"(a[2]), "r"(a[3]), "r"(b[0]), "r"(b[1]));
}
__device__ __forceinline__ uint32_t cvt_h2(float lo, float hi) {
    uint32_t r;
    asm("cvt.rn.f16x2.f32 %0, %1, %2;" : "=r"(r) : "f"(hi), "f"(lo));
    return r;
}
__device__ __forceinline__ uint32_t ex2_h2(uint32_t x) {
    uint32_t r;
    asm("ex2.approx.f16x2 %0, %1;" : "=r"(r) : "r"(x));
    return r;
}
__device__ __forceinline__ uint32_t swz128(int r, int c) {
    return (uint32_t)(r * 128 + ((c ^ (r & 7)) << 4));
}

// ============================================================================
// critical-path conversion: x + Wqkv + qkv bias (one kernel)
// ============================================================================
#define SEG_X   (MROWS * DMODEL / 4)          /* 1048576 */
#define SEG_QKV (3 * DMODEL * DMODEL / 4)     /* 786432 */
#define SEG_CP  (SEG_X + SEG_QKV)

__global__ void __launch_bounds__(256) cvt_cp_kernel(
    const float* __restrict__ X,
    const float* __restrict__ Wq, const float* __restrict__ Wk,
    const float* __restrict__ Wv,
    const float* __restrict__ bq, const float* __restrict__ bk,
    const float* __restrict__ bv,
    __half* __restrict__ XF, __half* __restrict__ QKVW,
    float* __restrict__ bpack)
{
    int i = blockIdx.x * 256 + threadIdx.x;
    if (i < 3 * DMODEL) {
        float b = (i < DMODEL) ? bq[i] : (i < 2 * DMODEL) ? bk[i - DMODEL]
                                                          : bv[i - 2 * DMODEL];
        bpack[i] = b;
    }
    if (i >= SEG_CP) return;

    const float* src;
    __half* F;
    int off;
    if (i < SEG_X) {
        off = i; src = X; F = XF;
    } else {
        const int n4m = DMODEL * DMODEL / 4;
        int r = i - SEG_X;
        int m = r / n4m;
        off = r - m * n4m;
        src = (m == 0) ? Wq : (m == 1) ? Wk : Wv;
        F = QKVW + (size_t)m * DMODEL * DMODEL;
    }
    float4 v = ((const float4*)src)[off];
    ((uint2*)F)[off] = make_uint2(cvt_h2(v.x, v.y), cvt_h2(v.z, v.w));
}

// ============================================================================
// off-path conversion: Wo + W1 + W2 (forked stream)
// ============================================================================
#define SEG_WO  (DMODEL * DMODEL / 4)
#define SEG_W1  (FFDIM * DMODEL / 4)
#define SEG_W2  (DMODEL * FFDIM / 4)
#define SEG_REST (SEG_WO + SEG_W1 + SEG_W2)

__global__ void __launch_bounds__(256) cvt_rest_kernel(
    const float* __restrict__ Wo, const float* __restrict__ W1,
    const float* __restrict__ W2,
    __half* __restrict__ WOF, __half* __restrict__ W1F,
    __half* __restrict__ W2F)
{
    int i = blockIdx.x * 256 + threadIdx.x;
    if (i >= SEG_REST) return;
    const float* src;
    __half* F;
    int off;
    if (i < SEG_WO) {
        off = i; src = Wo; F = WOF;
    } else if (i < SEG_WO + SEG_W1) {
        off = i - SEG_WO; src = W1; F = W1F;
    } else {
        off = i - SEG_WO - SEG_W1; src = W2; F = W2F;
    }
    float4 v = ((const float4*)src)[off];
    ((uint2*)F)[off] = make_uint2(cvt_h2(v.x, v.y), cvt_h2(v.z, v.w));
}

// ============================================================================
// fp16 GEMM (unchanged from R15)
// ============================================================================
#define TBM 128
#define TBN 128
#define TBK 64
#define STG_BYTES 32768
#define TG_SMEM (3 * STG_BYTES)

__device__ __forceinline__ void tg_load_stage(
    uint32_t sbuf, int t,
    const __half* __restrict__ Af, const __half* __restrict__ Bf,
    int rowBase, int colBase, int k0, int K)
{
#pragma unroll
    for (int j = 0; j < 8; j++) {
        int i   = j * 256 + t;
        int arr = i >> 10;
        int idx = i & 1023;
        int r   = idx >> 3;
        int ch  = idx & 7;
        const __half* base = arr ? Bf : Af;
        int gr = (arr ? colBase : rowBase) + r;
        cp16(sbuf + arr * 16384 + swz128(r, ch),
             base + (size_t)gr * K + k0 + ch * 8);
    }
    asm volatile("cp.async.commit_group;" ::: "memory");
}

template <bool RELU, int OUT>
__global__ void __launch_bounds__(256, 2) tgemm_kernel(
    const __half* __restrict__ Af, const __half* __restrict__ Bf,
    const float* __restrict__ bias, float* __restrict__ C,
    __half* __restrict__ F16O,
    int M, int N, int K)
{
    extern __shared__ __align__(16) char smem[];
    uint32_t sb = smem_u32(smem);
    const int t = threadIdx.x;
    const int w = t >> 5, lane = t & 31;
    const int wm = w >> 2;
    const int wn = w & 3;
    const int rowBase = blockIdx.y * TBM;
    const int colBase = blockIdx.x * TBN;
    const int KT = K / TBK;

    float acc[4][4][4];
#pragma unroll
    for (int mt = 0; mt < 4; mt++)
#pragma unroll
        for (int nt = 0; nt < 4; nt++)
#pragma unroll
            for (int e = 0; e < 4; e++) acc[mt][nt][e] = 0.f;

    tg_load_stage(sb,                 t, Af, Bf, rowBase, colBase, 0 * TBK, K);
    tg_load_stage(sb + 1 * STG_BYTES, t, Af, Bf, rowBase, colBase, 1 * TBK, K);

    int stage = 0;
    for (int kt = 0; kt < KT; kt++) {
        if (kt + 1 < KT)
            asm volatile("cp.async.wait_group 1;" ::: "memory");
        else
            asm volatile("cp.async.wait_group 0;" ::: "memory");
        __syncthreads();

        if (kt + 2 < KT) {
            int ps = stage + 2; if (ps >= 3) ps -= 3;
            tg_load_stage(sb + ps * STG_BYTES, t,
                          Af, Bf, rowBase, colBase, (kt + 2) * TBK, K);
        }

        uint32_t sbase = sb + stage * STG_BYTES;
#pragma unroll
        for (int ks = 0; ks < 4; ks++) {
            uint32_t ah[4][4];
            const int arow0  = wm * 64 + (lane & 15);
            const int achunk = ks * 2 + (lane >> 4);
#pragma unroll
            for (int mt = 0; mt < 4; mt++) {
                uint32_t off = swz128(arow0 + mt * 16, achunk);
                ldsm_x4(ah[mt][0], ah[mt][1], ah[mt][2], ah[mt][3], sbase + off);
            }
            const int brow = wn * 32 + ((lane >> 4) << 3) + (lane & 7);
            const int bch  = ks * 2 + ((lane >> 3) & 1);
#pragma unroll
            for (int np = 0; np < 2; np++) {
                uint32_t b2[4];
                uint32_t off = swz128(brow + np * 16, bch);
                ldsm_x4(b2[0], b2[1], b2[2], b2[3], sbase + 16384 + off);
#pragma unroll
                for (int mt = 0; mt < 4; mt++) {
                    mma_f16(acc[mt][2 * np],     ah[mt], b2);
                    mma_f16(acc[mt][2 * np + 1], ah[mt], b2 + 2);
                }
            }
        }
        stage++; if (stage == 3) stage = 0;
    }

#pragma unroll
    for (int nt = 0; nt < 4; nt++) {
        int c = colBase + wn * 32 + nt * 8 + (lane & 3) * 2;
        float b0 = __ldg(&bias[c]), b1 = __ldg(&bias[c + 1]);
#pragma unroll
        for (int mt = 0; mt < 4; mt++) {
            int r0 = rowBase + wm * 64 + mt * 16 + (lane >> 2);
            float v0 = acc[mt][nt][0] + b0, v1 = acc[mt][nt][1] + b1;
            float v2 = acc[mt][nt][2] + b0, v3 = acc[mt][nt][3] + b1;
            if (RELU) {
                v0 = fmaxf(v0, 0.f); v1 = fmaxf(v1, 0.f);
                v2 = fmaxf(v2, 0.f); v3 = fmaxf(v3, 0.f);
            }
            if (OUT == 0) {
                *(float2*)(C + (size_t)r0 * N + c)       = make_float2(v0, v1);
                *(float2*)(C + (size_t)(r0 + 8) * N + c) = make_float2(v2, v3);
            } else if (OUT == 1) {
                *(uint32_t*)(F16O + (size_t)r0 * N + c)       = cvt_h2(v0, v1);
                *(uint32_t*)(F16O + (size_t)(r0 + 8) * N + c) = cvt_h2(v2, v3);
            } else {
                int sel = c >> 10, cc = c & 1023;
                __half* dst = F16O + (size_t)sel * SLAB_ELEMS;
                *(uint32_t*)(dst + (size_t)r0 * DMODEL + cc)       = cvt_h2(v0, v1);
                *(uint32_t*)(dst + (size_t)(r0 + 8) * DMODEL + cc) = cvt_h2(v2, v3);
            }
        }
    }
}

// ============================================================================
// T5 relative-position bucket for displacement d
// ============================================================================
__device__ __forceinline__ int rel_bucket_d(int d)
{
    int ret = (d < 0) ? NHEAD : 0;
    int n   = abs(d);
    int b;
    if (n < 8) b = n;
    else {
        int j = (31 - __clz(n * n)) - 6;
        j = min(j, 7);
        b = 8 + j;
    }
    return ret + b;
}

// ============================================================================
// Fused flash attention — 64-key tiles, 3-stage KV pipeline, 2 blocks/SM.
// smem: Q 16K | KV stage x3 (K 8K + V 8K each = 48K) | lm 4K | bd 8K = 76K
// ============================================================================
#define AT_Q    0
#define AT_KV   16384          /* stage stride 16384 */
#define AT_LM   65536
#define AT_BD   69632
#define AT_SMEM 77824
#define KTILE   64
#define NKT     (LSEQ / KTILE)  /* 16 */

__device__ __forceinline__ void at_load_kv(
    uint32_t kvbase, int t, size_t slab, int kt,
    const __half* __restrict__ KF, const __half* __restrict__ VF)
{
    size_t gb = slab + (size_t)kt * KTILE * DHEAD;
    for (int i = t; i < 512; i += 256) {
        int r = i >> 3, c = i & 7;
        uint32_t off = swz128(r, c);
        size_t g = gb + r * DHEAD + c * 8;
        cp16(kvbase + off,        KF + g);
        cp16(kvbase + 8192 + off, VF + g);
    }
    asm volatile("cp.async.commit_group;" ::: "memory");
}

__global__ void __launch_bounds__(256, 2) attn_fused_kernel(
    const __half* __restrict__ QF,
    const __half* __restrict__ KF, const __half* __restrict__ VF,
    const float* __restrict__ rel, const int* __restrict__ pm,
    __half* __restrict__ OF)
{
    extern __shared__ __align__(16) char smem[];
    uint32_t sb = smem_u32(smem);
    float* lm_s = (float*)(smem + AT_LM);
    float* bd_s = (float*)(smem + AT_BD);

    const int t = threadIdx.x, w = t >> 5, lane = t & 31;
    const int qt = blockIdx.x, bh = blockIdx.y;
    const int h = bh & (NHEAD - 1), b = bh >> 4;
    const size_t slab = (size_t)bh * (LSEQ * DHEAD);

    for (int i = t; i < LSEQ; i += 256)
        lm_s[i] = log2f((float)pm[b * LSEQ + i]);
    for (int i = t; i < 2047; i += 256)
        bd_s[i] = rel[rel_bucket_d(i - 1023) * NHEAD + h] * LOG2E;

    {
        size_t qbase = slab + (size_t)qt * 128 * DHEAD;
        for (int i = t; i < 1024; i += 256) {
            int r = i >> 3, c = i & 7;
            cp16(sb + AT_Q + swz128(r, c), QF + qbase + r * DHEAD + c * 8);
        }
        at_load_kv(sb + AT_KV,             t, slab, 0, KF, VF);  // g0 (+Q)
        at_load_kv(sb + AT_KV + 16384,     t, slab, 1, KF, VF);  // g1
        at_load_kv(sb + AT_KV + 2 * 16384, t, slab, 2, KF, VF);  // g2
        asm volatile("cp.async.wait_group 2;" ::: "memory");     // Q + KV0
    }
    __syncthreads();

    uint32_t qf[4][4];
    {
        int r = w * 16 + (lane & 15);
#pragma unroll
        for (int ks = 0; ks < 4; ks++) {
            int c = ks * 2 + (lane >> 4);
            ldsm_x4(qf[ks][0], qf[ks][1], qf[ks][2], qf[ks][3],
                    sb + AT_Q + swz128(r, c));
        }
    }

    float O[8][4];
#pragma unroll
    for (int nt = 0; nt < 8; nt++)
#pragma unroll
        for (int e = 0; e < 4; e++) O[nt][e] = 0.f;
    float Lc[4] = {0.f, 0.f, 0.f, 0.f};
    float m0 = -3.0e38f, m1 = -3.0e38f;

    const uint32_t onesb[2] = {ONES_H2, ONES_H2};
    const int r0 = qt * 128 + w * 16 + (lane >> 2);
    const int r1 = r0 + 8;

    int stage = 0;
    for (int kt = 0; kt < NKT; kt++) {
        if (kt > 0) {
            // g(kt) must be done; up to 2 younger groups may be in flight
            int younger = NKT - 1 - kt; if (younger > 2) younger = 2;
            if (younger == 2)
                asm volatile("cp.async.wait_group 2;" ::: "memory");
            else if (younger == 1)
                asm volatile("cp.async.wait_group 1;" ::: "memory");
            else
                asm volatile("cp.async.wait_group 0;" ::: "memory");
            __syncthreads();
        }
        uint32_t kv = sb + AT_KV + stage * 16384;

        float S[8][4];
#pragma unroll
        for (int j = 0; j < 8; j++)
#pragma unroll
            for (int e = 0; e < 4; e++) S[j][e] = 0.f;

        // S = Q K^T over 64 keys
#pragma unroll
        for (int ks = 0; ks < 4; ks++) {
            const int krow = ((lane >> 4) << 3) + (lane & 7);
            const int kch  = ks * 2 + ((lane >> 3) & 1);
#pragma unroll
            for (int jq = 0; jq < 2; jq++) {
                uint32_t kb0[4], kb1[4];
                uint32_t off0 = swz128((2 * jq) * 16 + krow, kch);
                uint32_t off1 = swz128((2 * jq + 1) * 16 + krow, kch);
                ldsm_x4(kb0[0], kb0[1], kb0[2], kb0[3], kv + off0);
                ldsm_x4(kb1[0], kb1[1], kb1[2], kb1[3], kv + off1);
                mma_f16(S[4 * jq + 0], qf[ks], kb0);
                mma_f16(S[4 * jq + 1], qf[ks], kb0 + 2);
                mma_f16(S[4 * jq + 2], qf[ks], kb1);
                mma_f16(S[4 * jq + 3], qf[ks], kb1 + 2);
            }
        }

        // fused bias (log2 domain) + tile max
        const int ktbase = kt * KTILE;
        float tm0 = -3.0e38f, tm1 = -3.0e38f;
#pragma unroll
        for (int j = 0; j < 8; j++) {
            int c = ktbase + j * 8 + (lane & 3) * 2;
            float t00 = bd_s[c - r0 + 1023] + lm_s[c];
            float t01 = bd_s[c + 1 - r0 + 1023] + lm_s[c + 1];
            float t10 = bd_s[c - r1 + 1023] + lm_s[c];
            float t11 = bd_s[c + 1 - r1 + 1023] + lm_s[c + 1];
            S[j][0] = fmaf(S[j][0], LOG2E, t00);
            S[j][1] = fmaf(S[j][1], LOG2E, t01);
            S[j][2] = fmaf(S[j][2], LOG2E, t10);
            S[j][3] = fmaf(S[j][3], LOG2E, t11);
            tm0 = fmaxf(tm0, fmaxf(S[j][0], S[j][1]));
            tm1 = fmaxf(tm1, fmaxf(S[j][2], S[j][3]));
        }
        tm0 = fmaxf(tm0, __shfl_xor_sync(0xffffffffu, tm0, 1));
        tm0 = fmaxf(tm0, __shfl_xor_sync(0xffffffffu, tm0, 2));
        tm1 = fmaxf(tm1, __shfl_xor_sync(0xffffffffu, tm1, 1));
        tm1 = fmaxf(tm1, __shfl_xor_sync(0xffffffffu, tm1, 2));
        float mn0 = fmaxf(m0, tm0), mn1 = fmaxf(m1, tm1);
        float a0 = exp2f(m0 - mn0), a1 = exp2f(m1 - mn1);
        m0 = mn0; m1 = mn1;

#pragma unroll
        for (int nt = 0; nt < 8; nt++) {
            O[nt][0] *= a0; O[nt][1] *= a0;
            O[nt][2] *= a1; O[nt][3] *= a1;
        }
        Lc[0] *= a0; Lc[1] *= a0; Lc[2] *= a1; Lc[3] *= a1;

        // P = exp2(S - m) in f16x2; O += P@V; L += P@1
#pragma unroll
        for (int kk = 0; kk < 4; kk++) {
            float* p0 = S[2 * kk];
            float* p1 = S[2 * kk + 1];
            uint32_t ph[4];
            ph[0] = ex2_h2(cvt_h2(p0[0] - mn0, p0[1] - mn0));
            ph[1] = ex2_h2(cvt_h2(p0[2] - mn1, p0[3] - mn1));
            ph[2] = ex2_h2(cvt_h2(p1[0] - mn0, p1[1] - mn0));
            ph[3] = ex2_h2(cvt_h2(p1[2] - mn1, p1[3] - mn1));
            const int vrow = kk * 16 + (lane & 15);
            const int vcp  = (lane >> 4) & 1;
#pragma unroll
            for (int np = 0; np < 4; np++) {
                uint32_t vb[4];
                uint32_t off = swz128(vrow, np * 2 + vcp);
                ldsm_x4t(vb[0], vb[1], vb[2], vb[3], kv + 8192 + off);
                mma_f16(O[2 * np],     ph, vb);
                mma_f16(O[2 * np + 1], ph, vb + 2);
            }
            mma_f16(Lc, ph, onesb);
        }

        __syncthreads();
        if (kt + 3 < NKT)
            at_load_kv(sb + AT_KV + stage * 16384, t, slab, kt + 3, KF, VF);
        stage++; if (stage == 3) stage = 0;
    }

    float inv0 = 1.f / Lc[0], inv1 = 1.f / Lc[2];
    size_t ob0 = slab + (size_t)(qt * 128 + w * 16 + (lane >> 2)) * DHEAD;
    size_t ob1 = ob0 + 8 * DHEAD;
#pragma unroll
    for (int nt = 0; nt < 8; nt++) {
        int c = nt * 8 + (lane & 3) * 2;
        *(uint32_t*)(OF + ob0 + c) = cvt_h2(O[nt][0] * inv0, O[nt][1] * inv0);
        *(uint32_t*)(OF + ob1 + c) = cvt_h2(O[nt][2] * inv1, O[nt][3] * inv1);
    }
}

// ============================================================================
// out = LayerNorm(A + B); optional fp16 side output
// ============================================================================
template <bool SPLIT>
__global__ void __launch_bounds__(256) add_ln_kernel(
    const float* __restrict__ A, const float* __restrict__ B,
    float* __restrict__ out, __half* __restrict__ OF)
{
    __shared__ float sh[8];
    const size_t row = blockIdx.x;
    const int t = threadIdx.x;

    float4 a = ((const float4*)(A + row * DMODEL))[t];
    float4 b = ((const float4*)(B + row * DMODEL))[t];
    float4 x;
    x.x = a.x + b.x; x.y = a.y + b.y; x.z = a.z + b.z; x.w = a.w + b.w;

    float s = x.x + x.y + x.z + x.w;
#pragma unroll
    for (int o = 16; o; o >>= 1) s += __shfl_xor_sync(0xffffffffu, s, o);
    if ((t & 31) == 0) sh[t >> 5] = s;
    __syncthreads();
    float tot = sh[0];
#pragma unroll
    for (int i = 1; i < 8; i++) tot += sh[i];
    __syncthreads();
    float mean = tot * (1.f / DMODEL);

    float dx = x.x - mean, dy = x.y - mean, dz = x.z - mean, dw = x.w - mean;
    float s2 = dx * dx + dy * dy + dz * dz + dw * dw;
#pragma unroll
    for (int o = 16; o; o >>= 1) s2 += __shfl_xor_sync(0xffffffffu, s2, o);
    if ((t & 31) == 0) sh[t >> 5] = s2;
    __syncthreads();
    float tot2 = sh[0];
#pragma unroll
    for (int i = 1; i < 8; i++) tot2 += sh[i];
    float inv = rsqrtf(tot2 * (1.f / DMODEL));

    float4 o;
    o.x = dx * inv; o.y = dy * inv; o.z = dz * inv; o.w = dw * inv;
    ((float4*)(out + row * DMODEL))[t] = o;

    if (SPLIT) {
        size_t base = row * DMODEL + t * 4;
        *(uint32_t*)(OF + base)     = cvt_h2(o.x, o.y);
        *(uint32_t*)(OF + base + 2) = cvt_h2(o.z, o.w);
    }
}

// ============================================================================
// Launch sequence (main stream + forked side stream for off-path weight cvt)
// ============================================================================
extern "C" void kernel_launch(void* const* d_in, const int* in_sizes, int n_in,
                              void* d_out, int out_size)
{
    const float* x   = (const float*)d_in[0];
    const int*   pm  = (const int*)  d_in[1];
    const float* Wq  = (const float*)d_in[2];
    const float* bq  = (const float*)d_in[3];
    const float* Wk  = (const float*)d_in[4];
    const float* bk  = (const float*)d_in[5];
    const float* Wv  = (const float*)d_in[6];
    const float* bv  = (const float*)d_in[7];
    const float* Wo  = (const float*)d_in[8];
    const float* bo  = (const float*)d_in[9];
    const float* rel = (const float*)d_in[10];
    const float* W1  = (const float*)d_in[11];
    const float* b1  = (const float*)d_in[12];
    const float* W2  = (const float*)d_in[13];
    const float* b2  = (const float*)d_in[14];
    float* out = (float*)d_out;

    float *attp, *attout, *ff, *bqkv;
    cudaGetSymbolAddress((void**)&attp,   g_attp);
    cudaGetSymbolAddress((void**)&attout, g_attout);
    cudaGetSymbolAddress((void**)&ff,     g_ff);
    cudaGetSymbolAddress((void**)&bqkv,   g_bqkv);

    __half *xf, *wqkv, *wo, *w1, *w2, *qkv, *avf, *aof, *h1f;
    cudaGetSymbolAddress((void**)&xf,   g_xf);
    cudaGetSymbolAddress((void**)&wqkv, g_wqkv);
    cudaGetSymbolAddress((void**)&wo,   g_wo);
    cudaGetSymbolAddress((void**)&w1,   g_w1);
    cudaGetSymbolAddress((void**)&w2,   g_w2);
    cudaGetSymbolAddress((void**)&qkv,  g_qkv);
    cudaGetSymbolAddress((void**)&avf,  g_avf);
    cudaGetSymbolAddress((void**)&aof,  g_aof);
    cudaGetSymbolAddress((void**)&h1f,  g_h1f);

    static bool init_done = false;
    static cudaStream_t s2;
    static cudaEvent_t ev_fork, ev_join;
    if (!init_done) {
        cudaFuncSetAttribute(tgemm_kernel<false, 0>,
                             cudaFuncAttributeMaxDynamicSharedMemorySize, TG_SMEM);
        cudaFuncSetAttribute(tgemm_kernel<false, 2>,
                             cudaFuncAttributeMaxDynamicSharedMemorySize, TG_SMEM);
        cudaFuncSetAttribute(tgemm_kernel<true, 1>,
                             cudaFuncAttributeMaxDynamicSharedMemorySize, TG_SMEM);
        cudaFuncSetAttribute(attn_fused_kernel,
                             cudaFuncAttributeMaxDynamicSharedMemorySize, AT_SMEM);
        cudaStreamCreateWithFlags(&s2, cudaStreamNonBlocking);
        cudaEventCreateWithFlags(&ev_fork, cudaEventDisableTiming);
        cudaEventCreateWithFlags(&ev_join, cudaEventDisableTiming);
        init_done = true;
    }

    dim3 blk(256);

    // L1: critical-path conversion (x + Wqkv + bias)
    cvt_cp_kernel<<<(SEG_CP + 255) / 256, blk>>>(
        x, Wq, Wk, Wv, bq, bk, bv, xf, wqkv, bqkv);

    // fork: off-path weight conversion on side stream (overlaps QKV+attention)
    cudaEventRecord(ev_fork, 0);
    cudaStreamWaitEvent(s2, ev_fork, 0);
    cvt_rest_kernel<<<(SEG_REST + 255) / 256, blk, 0, s2>>>(
        Wo, W1, W2, wo, w1, w2);
    cudaEventRecord(ev_join, s2);

    // QKV projection
    dim3 gqkv(3 * DMODEL / TBN, MROWS / TBM);
    tgemm_kernel<false, 2><<<gqkv, blk, TG_SMEM>>>(
        xf, wqkv, bqkv, nullptr, qkv, MROWS, 3 * DMODEL, DMODEL);

    // attention
    attn_fused_kernel<<<dim3(8, BHDIM), blk, AT_SMEM>>>(
        qkv, qkv + SLAB_ELEMS, qkv + 2 * SLAB_ELEMS, rel, pm, avf);

    // join before first use of converted Wo/W1/W2
    cudaStreamWaitEvent(0, ev_join, 0);

    // O projection
    dim3 gO(DMODEL / TBN, MROWS / TBM);
    tgemm_kernel<false, 0><<<gO, blk, TG_SMEM>>>(
        avf, wo, bo, attp, nullptr, MROWS, DMODEL, DMODEL);

    add_ln_kernel<true><<<MROWS, blk>>>(attp, x, attout, aof);

    dim3 g1(FFDIM / TBN, MROWS / TBM);
    tgemm_kernel<true, 1><<<g1, blk, TG_SMEM>>>(
        aof, w1, b1, nullptr, h1f, MROWS, FFDIM, DMODEL);
    dim3 g2(DMODEL / TBN, MROWS / TBM);
    tgemm_kernel<false, 0><<<g2, blk, TG_SMEM>>>(
        h1f, w2, b2, ff, nullptr, MROWS, DMODEL, FFDIM);

    add_ln_kernel<false><<<MROWS, blk>>>(ff, attout, out, nullptr);
}